// round 3
// baseline (speedup 1.0000x reference)
#include <cuda_runtime.h>

// Problem constants (fixed by setup_inputs): B=8, N=20, K=5, Q=15, D=1024
#define BB     8
#define NN     20
#define KSUP   5
#define QQ     15
#define DD     1024
#define ROWS   (KSUP + QQ)        // 20 rows per (b,n)
#define NQ     (NN * QQ)          // 300 queries per batch
#define PAIRS_PER_B (NQ / 2)      // 150
#define TASKS  (BB * PAIRS_PER_B) // 1200 query-pair tasks
#define WARPS  8
#define THREADS 256
#define GRID   (TASKS / WARPS)    // 150 blocks, 1 task/warp, single wave

// NOTE: 1 ulonglong2 = 16 B = 4 floats. A D=1024 row = 256 ulonglong2.
#define ROW_U2 256

typedef unsigned long long u64;

// Scratch (device globals — no allocation allowed)
__device__ float g_proto[BB * NN * DD];   // 640 KB, L2-resident
__device__ float g_termp[BB * NN];

// ---- packed f32x2 helpers (sm_103a) ----
__device__ __forceinline__ u64 mul2(u64 a, u64 b) {
    u64 r; asm("mul.rn.f32x2 %0,%1,%2;" : "=l"(r) : "l"(a), "l"(b)); return r;
}
__device__ __forceinline__ u64 add2(u64 a, u64 b) {
    u64 r; asm("add.rn.f32x2 %0,%1,%2;" : "=l"(r) : "l"(a), "l"(b)); return r;
}
__device__ __forceinline__ u64 fma2_(u64 a, u64 b, u64 c) {
    u64 r; asm("fma.rn.f32x2 %0,%1,%2,%3;" : "=l"(r) : "l"(a), "l"(b), "l"(c)); return r;
}
__device__ __forceinline__ u64 abs2(u64 a) {
    u64 r; asm("and.b64 %0,%1,0x7FFFFFFF7FFFFFFF;" : "=l"(r) : "l"(a)); return r;
}
__device__ __forceinline__ u64 neg2(u64 a) {
    u64 r; asm("xor.b64 %0,%1,0x8000000080000000;" : "=l"(r) : "l"(a)); return r;
}
__device__ __forceinline__ float hsum2(u64 a) {
    float x, y; asm("mov.b64 {%0,%1},%2;" : "=f"(x), "=f"(y) : "l"(a)); return x + y;
}

// ---------------------------------------------------------------------------
// K1: proto[b,n,:] = mean_j support, term_p[b,n] = proto . w0
// ---------------------------------------------------------------------------
__global__ __launch_bounds__(256) void proto_kernel(
    const float* __restrict__ emb, const float* __restrict__ weight)
{
    int bn = blockIdx.x;             // b*20 + n
    int t  = threadIdx.x;            // float4 index 0..255
    const float4* base = reinterpret_cast<const float4*>(emb) + (size_t)bn * ROWS * 256;

    float4 s = base[t];
#pragma unroll
    for (int j = 1; j < KSUP; j++) {
        float4 v = base[j * 256 + t];
        s.x += v.x; s.y += v.y; s.z += v.z; s.w += v.w;
    }
    s.x *= 0.2f; s.y *= 0.2f; s.z *= 0.2f; s.w *= 0.2f;
    reinterpret_cast<float4*>(g_proto)[(size_t)bn * 256 + t] = s;

    float4 w0 = reinterpret_cast<const float4*>(weight)[t];
    float tp = s.x * w0.x + s.y * w0.y + s.z * w0.z + s.w * w0.w;
#pragma unroll
    for (int off = 16; off; off >>= 1) tp += __shfl_xor_sync(0xFFFFFFFFu, tp, off);

    __shared__ float red[8];
    if ((t & 31) == 0) red[t >> 5] = tp;
    __syncthreads();
    if (t == 0) {
        float r = 0.f;
#pragma unroll
        for (int w = 0; w < 8; w++) r += red[w];
        g_termp[bn] = r;
    }
}

// ---------------------------------------------------------------------------
// Main: 150 blocks x 256 threads, exactly one query-pair per warp, single
// wave. All 20 n-accumulators live in registers (two passes of 10, packed
// f32x2); lane-reductions deferred to end of pass => no serial shfl chains.
// Inner (i,n): 1 LDS.128 (serves both queries) + 12 packed fma-pipe ops.
// ---------------------------------------------------------------------------
__global__ __launch_bounds__(THREADS, 1) void relnet_kernel(
    const float* __restrict__ emb,
    const float* __restrict__ weight,
    const float* __restrict__ bias,
    float* __restrict__ out)
{
    extern __shared__ float smem[];
    ulonglong2* sP  = reinterpret_cast<ulonglong2*>(smem);                  // 20*256 u2 = 81920 B
    ulonglong2* sW2 = reinterpret_cast<ulonglong2*>(smem + NN * DD);        // 256 u2   =  4096 B
    float*      sTp = smem + NN * DD + 1024;                                // 20 floats

    const int tid  = threadIdx.x;
    const int lane = tid & 31;
    const int warp = tid >> 5;

    const int task = blockIdx.x * WARPS + warp;          // 0..1199, always valid
    const int bMy  = task / PAIRS_PER_B;
    const int q0   = (task - bMy * PAIRS_PER_B) * 2;     // even query idx in batch
    const int q1   = q0 + 1;
    const int bLo  = (blockIdx.x * WARPS) / PAIRS_PER_B;
    const int bHi  = (blockIdx.x * WARPS + WARPS - 1) / PAIRS_PER_B;

    const ulonglong2* embu = reinterpret_cast<const ulonglong2*>(emb);
    const ulonglong2* w1u  = reinterpret_cast<const ulonglong2*>(weight) + 1 * ROW_U2;
    const ulonglong2* w2u  = reinterpret_cast<const ulonglong2*>(weight) + 2 * ROW_U2;
    const ulonglong2* w3u  = reinterpret_cast<const ulonglong2*>(weight) + 3 * ROW_U2;
    const ulonglong2* gPu  = reinterpret_cast<const ulonglong2*>(g_proto);
    const float bi = bias[0];

    // ---- load query pair into registers (negated q, and q*w3), packed ----
    const int r0row = (bMy * NN + q0 / QQ) * ROWS + KSUP + q0 % QQ;
    const int r1row = (bMy * NN + q1 / QQ) * ROWS + KSUP + q1 % QQ;
    const ulonglong2* r0 = embu + (size_t)r0row * ROW_U2;
    const ulonglong2* r1 = embu + (size_t)r1row * ROW_U2;

    u64 qn0[16], qn1[16], c0[16], c1[16];
    u64 tq0p = 0ull, tq1p = 0ull;
#pragma unroll
    for (int i = 0; i < 8; i++) {
        const int idx = i * 32 + lane;
        ulonglong2 a  = r0[idx];
        ulonglong2 b  = r1[idx];
        ulonglong2 w3 = w3u[idx];
        ulonglong2 w1 = w1u[idx];
        qn0[2*i]   = neg2(a.x);  qn0[2*i+1] = neg2(a.y);
        qn1[2*i]   = neg2(b.x);  qn1[2*i+1] = neg2(b.y);
        c0[2*i]    = mul2(a.x, w3.x);  c0[2*i+1] = mul2(a.y, w3.y);
        c1[2*i]    = mul2(b.x, w3.x);  c1[2*i+1] = mul2(b.y, w3.y);
        tq0p = fma2_(a.x, w1.x, tq0p); tq0p = fma2_(a.y, w1.y, tq0p);
        tq1p = fma2_(b.x, w1.x, tq1p); tq1p = fma2_(b.y, w1.y, tq1p);
    }
    float tq0 = hsum2(tq0p), tq1 = hsum2(tq1p);
#pragma unroll
    for (int off = 16; off; off >>= 1) {
        tq0 += __shfl_xor_sync(0xFFFFFFFFu, tq0, off);
        tq1 += __shfl_xor_sync(0xFFFFFFFFu, tq1, off);
    }

    float* o0 = out + ((size_t)bMy * NQ + q0) * NN;
    float* o1 = o0 + NN;

#pragma unroll 1
    for (int b = bLo; b <= bHi; b++) {
        __syncthreads();   // protect smem from previous iteration's readers
        for (int idx = tid; idx < NN * ROW_U2; idx += THREADS)
            sP[idx] = gPu[(size_t)b * NN * ROW_U2 + idx];
        sW2[tid] = w2u[tid];                      // 256 u2 = full w2 row
        if (tid < NN) sTp[tid] = g_termp[b * NN + tid];
        __syncthreads();
        if (bMy != b) continue;

#pragma unroll 1
        for (int pass = 0; pass < 2; pass++) {
            u64 a0[10], a1[10];
#pragma unroll
            for (int n = 0; n < 10; n++) { a0[n] = 0ull; a1[n] = 0ull; }

            const ulonglong2* pb = sP + pass * 10 * ROW_U2 + lane;
#pragma unroll
            for (int i = 0; i < 8; i++) {
                const ulonglong2 w2 = sW2[i * 32 + lane];
#pragma unroll
                for (int n = 0; n < 10; n++) {
                    const ulonglong2 p = pb[n * ROW_U2 + i * 32];
                    u64 d;
                    d = abs2(add2(p.x, qn0[2*i]));
                    a0[n] = fma2_(d, w2.x, a0[n]);
                    a0[n] = fma2_(p.x, c0[2*i], a0[n]);
                    d = abs2(add2(p.y, qn0[2*i+1]));
                    a0[n] = fma2_(d, w2.y, a0[n]);
                    a0[n] = fma2_(p.y, c0[2*i+1], a0[n]);
                    d = abs2(add2(p.x, qn1[2*i]));
                    a1[n] = fma2_(d, w2.x, a1[n]);
                    a1[n] = fma2_(p.x, c1[2*i], a1[n]);
                    d = abs2(add2(p.y, qn1[2*i+1]));
                    a1[n] = fma2_(d, w2.y, a1[n]);
                    a1[n] = fma2_(p.y, c1[2*i+1], a1[n]);
                }
            }

            // deferred reductions: 20 independent butterflies, full ILP
#pragma unroll
            for (int n = 0; n < 10; n++) {
                float s0 = hsum2(a0[n]);
                float s1 = hsum2(a1[n]);
#pragma unroll
                for (int off = 16; off; off >>= 1) {
                    s0 += __shfl_xor_sync(0xFFFFFFFFu, s0, off);
                    s1 += __shfl_xor_sync(0xFFFFFFFFu, s1, off);
                }
                if (lane == 0) {
                    const int nn = pass * 10 + n;
                    const float tp = sTp[nn];
                    o0[nn] = s0 + tp + tq0 + bi;
                    o1[nn] = s1 + tp + tq1 + bi;
                }
            }
        }
    }
}

// ---------------------------------------------------------------------------
// Launch
// ---------------------------------------------------------------------------
static const int SMEM_BYTES = (NN * DD + 1024 + 32) * (int)sizeof(float); // 86,144 B

extern "C" void kernel_launch(void* const* d_in, const int* in_sizes, int n_in,
                              void* d_out, int out_size)
{
    const float* emb    = (const float*)d_in[0];
    const float* weight = (const float*)d_in[1];
    const float* bias   = (const float*)d_in[2];
    float* out          = (float*)d_out;

    cudaFuncSetAttribute(relnet_kernel,
                         cudaFuncAttributeMaxDynamicSharedMemorySize, SMEM_BYTES);

    proto_kernel<<<BB * NN, 256>>>(emb, weight);
    relnet_kernel<<<GRID, THREADS, SMEM_BYTES>>>(emb, weight, bias, out);
}

// round 4
// speedup vs baseline: 1.4467x; 1.4467x over previous
#include <cuda_runtime.h>

// Problem constants (fixed by setup_inputs): B=8, N=20, K=5, Q=15, D=1024
#define BB     8
#define NN     20
#define KSUP   5
#define QQ     15
#define DD     1024
#define ROWS   (KSUP + QQ)        // 20 rows per (b,n)
#define NQ     (NN * QQ)          // 300 queries per batch
#define NQTOT  (BB * NQ)          // 2400 queries total
#define WARPS  16
#define THREADS 512
#define GRID   (NQTOT / WARPS)    // 150 blocks, 1 query/warp, single wave

// Scratch (device globals — no allocation allowed)
__device__ float g_proto[BB * NN * DD];   // 640 KB, L2-resident
__device__ float g_termp[BB * NN];

// ---------------------------------------------------------------------------
// K1: proto[b,n,:] = mean_j support, term_p[b,n] = proto . w0
// ---------------------------------------------------------------------------
__global__ __launch_bounds__(256) void proto_kernel(
    const float* __restrict__ emb, const float* __restrict__ weight)
{
    int bn = blockIdx.x;             // b*20 + n
    int t  = threadIdx.x;            // float4 index 0..255
    const float4* base = reinterpret_cast<const float4*>(emb) + (size_t)bn * ROWS * 256;

    float4 s = base[t];
#pragma unroll
    for (int j = 1; j < KSUP; j++) {
        float4 v = base[j * 256 + t];
        s.x += v.x; s.y += v.y; s.z += v.z; s.w += v.w;
    }
    s.x *= 0.2f; s.y *= 0.2f; s.z *= 0.2f; s.w *= 0.2f;
    reinterpret_cast<float4*>(g_proto)[(size_t)bn * 256 + t] = s;

    float4 w0 = reinterpret_cast<const float4*>(weight)[t];
    float tp = s.x * w0.x + s.y * w0.y + s.z * w0.z + s.w * w0.w;
#pragma unroll
    for (int off = 16; off; off >>= 1) tp += __shfl_xor_sync(0xFFFFFFFFu, tp, off);

    __shared__ float red[8];
    if ((t & 31) == 0) red[t >> 5] = tp;
    __syncthreads();
    if (t == 0) {
        float r = 0.f;
#pragma unroll
        for (int w = 0; w < 8; w++) r += red[w];
        g_termp[bn] = r;
    }
}

// ---------------------------------------------------------------------------
// Main: 150 blocks x 512 threads (16 warps), ONE query per warp, single wave.
// All 20 n-accumulators live in registers (single pass, plain float — abs
// folds into FFMA/FADD source modifiers). Lane reductions deferred to the end:
// 20 independent shfl butterflies. Occupancy doubled vs R1/R3 (4 warps/SMSP).
// ---------------------------------------------------------------------------
__global__ __launch_bounds__(THREADS, 1) void relnet_kernel(
    const float* __restrict__ emb,
    const float* __restrict__ weight,
    const float* __restrict__ bias,
    float* __restrict__ out)
{
    extern __shared__ float smem[];
    float4* sP4 = reinterpret_cast<float4*>(smem);               // 20*256 f4 = 81920 B
    float4* sW2 = reinterpret_cast<float4*>(smem + NN * DD);     // 256 f4    =  4096 B
    float*  sTp = smem + NN * DD + 1024;                         // 20 floats

    const int tid  = threadIdx.x;
    const int lane = tid & 31;
    const int warp = tid >> 5;

    const int g   = blockIdx.x * WARPS + warp;   // global query id 0..2399
    const int bMy = g / NQ;
    const int q   = g - bMy * NQ;                // query idx within batch
    const int bLo = (blockIdx.x * WARPS) / NQ;
    const int bHi = (blockIdx.x * WARPS + WARPS - 1) / NQ;

    const float4* emb4 = reinterpret_cast<const float4*>(emb);
    const float4* w14  = reinterpret_cast<const float4*>(weight) + 1 * 256;
    const float4* w24  = reinterpret_cast<const float4*>(weight) + 2 * 256;
    const float4* w34  = reinterpret_cast<const float4*>(weight) + 3 * 256;
    const float4* gP4  = reinterpret_cast<const float4*>(g_proto);
    const float bi = bias[0];

    // ---- load this warp's query into registers: q and q*w3; fold term_q ----
    const int qrow = (bMy * NN + q / QQ) * ROWS + KSUP + q % QQ;
    const float4* r = emb4 + (size_t)qrow * 256;

    float qv[32], cv[32];
    float tq = 0.f;
#pragma unroll
    for (int i = 0; i < 8; i++) {
        const int idx = i * 32 + lane;
        float4 a  = r[idx];
        float4 w3 = w34[idx];
        float4 w1 = w14[idx];
        qv[4*i+0] = a.x; qv[4*i+1] = a.y; qv[4*i+2] = a.z; qv[4*i+3] = a.w;
        cv[4*i+0] = a.x * w3.x; cv[4*i+1] = a.y * w3.y;
        cv[4*i+2] = a.z * w3.z; cv[4*i+3] = a.w * w3.w;
        tq = fmaf(a.x, w1.x, tq); tq = fmaf(a.y, w1.y, tq);
        tq = fmaf(a.z, w1.z, tq); tq = fmaf(a.w, w1.w, tq);
    }
#pragma unroll
    for (int off = 16; off; off >>= 1) tq += __shfl_xor_sync(0xFFFFFFFFu, tq, off);

    float* o = out + ((size_t)bMy * NQ + q) * NN;

#pragma unroll 1
    for (int b = bLo; b <= bHi; b++) {
        __syncthreads();   // protect smem from previous iteration's readers
        for (int idx = tid; idx < NN * 256; idx += THREADS)
            sP4[idx] = gP4[(size_t)b * NN * 256 + idx];
        if (tid < 256) sW2[tid] = w24[tid];
        if (tid < NN)  sTp[tid] = g_termp[b * NN + tid];
        __syncthreads();
        if (bMy != b) continue;

        float acc[NN];
#pragma unroll
        for (int n = 0; n < NN; n++) acc[n] = 0.f;

#pragma unroll
        for (int i = 0; i < 8; i++) {
            const float4 w2 = sW2[i * 32 + lane];
            const float4* pb = sP4 + i * 32 + lane;
#pragma unroll
            for (int n = 0; n < NN; n++) {
                const float4 p = pb[n * 256];
                acc[n] = fmaf(fabsf(p.x - qv[4*i+0]), w2.x, acc[n]);
                acc[n] = fmaf(p.x, cv[4*i+0], acc[n]);
                acc[n] = fmaf(fabsf(p.y - qv[4*i+1]), w2.y, acc[n]);
                acc[n] = fmaf(p.y, cv[4*i+1], acc[n]);
                acc[n] = fmaf(fabsf(p.z - qv[4*i+2]), w2.z, acc[n]);
                acc[n] = fmaf(p.z, cv[4*i+2], acc[n]);
                acc[n] = fmaf(fabsf(p.w - qv[4*i+3]), w2.w, acc[n]);
                acc[n] = fmaf(p.w, cv[4*i+3], acc[n]);
            }
        }

        // deferred reductions: 20 independent butterflies, full ILP
#pragma unroll
        for (int n = 0; n < NN; n++) {
            float s = acc[n];
#pragma unroll
            for (int off = 16; off; off >>= 1)
                s += __shfl_xor_sync(0xFFFFFFFFu, s, off);
            acc[n] = s;
        }
        if (lane == 0) {
#pragma unroll
            for (int n = 0; n < NN; n++)
                o[n] = acc[n] + sTp[n] + tq + bi;
        }
    }
}

// ---------------------------------------------------------------------------
// Launch
// ---------------------------------------------------------------------------
static const int SMEM_BYTES = (NN * DD + 1024 + 32) * (int)sizeof(float); // 86,144 B

extern "C" void kernel_launch(void* const* d_in, const int* in_sizes, int n_in,
                              void* d_out, int out_size)
{
    const float* emb    = (const float*)d_in[0];
    const float* weight = (const float*)d_in[1];
    const float* bias   = (const float*)d_in[2];
    float* out          = (float*)d_out;

    cudaFuncSetAttribute(relnet_kernel,
                         cudaFuncAttributeMaxDynamicSharedMemorySize, SMEM_BYTES);

    proto_kernel<<<BB * NN, 256>>>(emb, weight);
    relnet_kernel<<<GRID, THREADS, SMEM_BYTES>>>(emb, weight, bias, out);
}